// round 17
// baseline (speedup 1.0000x reference)
#include <cuda_runtime.h>
#include <cuda_fp16.h>
#include <cstdint>

// ---------------------------------------------------------------------------
// Problem constants
// ---------------------------------------------------------------------------
#define Bsz    2
#define Lseq   1024
#define VOC    32000
#define Dm     512
#define NLAY   2
#define INNER  1024
#define MLPD   2048
#define NSEG   8
#define SEGLEN 128
#define NROWS  (Bsz*Lseq)      // 2048 base rows
#define XROWS  (2*NROWS)       // 4096 merged rows
#define DEC_SK 5
#define DEC_KSLICE (VOC/DEC_SK)   // 6400 (divisible by 128)
#define NCH    16
#define CHLEN  (Lseq/NCH)         // 64

// ---------------------------------------------------------------------------
// Scratch
// ---------------------------------------------------------------------------
__device__ float g_x      [XROWS * Dm];
__device__ float g_decpart[DEC_SK * NROWS * Dm];
__device__ float g_ug     [XROWS * 2 * INNER];
__device__ float g_state  [NLAY * Bsz * NSEG * INNER];
__device__ float g_carry  [Bsz * NCH * INNER];
__device__ float g_sin    [Bsz * NCH * INNER];
__device__ float g_last   [Bsz * NSEG * Dm];
__device__ int   g_starts [Bsz * NSEG];
__device__ int   g_ends   [Bsz * NSEG];
__device__ __half g_decAw[NROWS * VOC];
__device__ __half g_xw   [XROWS * Dm];
__device__ __half g_pw   [XROWS * INNER];
__device__ __half g_mlpw [XROWS * MLPD];
__device__ __half g_Ew   [VOC * Dm];
__device__ __half g_Winw [NLAY * Dm * 2 * INNER];
__device__ __half g_Woutw[NLAY * INNER * Dm];
__device__ __half g_Wm1w [NLAY * Dm * MLPD];
__device__ __half g_Wm2w [NLAY * MLPD * Dm];

__device__ __forceinline__ float silu_f(float v) { return v * (1.f / (1.f + __expf(-v))); }

__device__ __forceinline__ uint32_t cvt2h(float a, float b) {
    return (uint32_t)__half_as_ushort(__float2half_rn(a))
         | ((uint32_t)__half_as_ushort(__float2half_rn(b)) << 16);
}

// ---------------------------------------------------------------------------
// primitives
// ---------------------------------------------------------------------------
__device__ __forceinline__ uint32_t smem_u32(const void* p) {
    return (uint32_t)__cvta_generic_to_shared(p);
}
__device__ __forceinline__ void ldmA(uint32_t* r, uint32_t addr) {
    asm volatile("ldmatrix.sync.aligned.m8n8.x4.shared.b16 {%0,%1,%2,%3}, [%4];"
                 : "=r"(r[0]), "=r"(r[1]), "=r"(r[2]), "=r"(r[3]) : "r"(addr));
}
__device__ __forceinline__ void ldmT(uint32_t& r0, uint32_t& r1, uint32_t& r2, uint32_t& r3,
                                     uint32_t addr) {
    asm volatile("ldmatrix.sync.aligned.m8n8.x4.trans.shared.b16 {%0,%1,%2,%3}, [%4];"
                 : "=r"(r0), "=r"(r1), "=r"(r2), "=r"(r3) : "r"(addr));
}
__device__ __forceinline__ void mma16816(float* c, const uint32_t* a, const uint32_t* b) {
    asm volatile("mma.sync.aligned.m16n8k16.row.col.f32.f16.f16.f32 "
                 "{%0,%1,%2,%3}, {%4,%5,%6,%7}, {%8,%9}, {%0,%1,%2,%3};"
                 : "+f"(c[0]), "+f"(c[1]), "+f"(c[2]), "+f"(c[3])
                 : "r"(a[0]), "r"(a[1]), "r"(a[2]), "r"(a[3]), "r"(b[0]), "r"(b[1]));
}
__device__ __forceinline__ void cpa16(uint32_t s, const void* g) {
    asm volatile("cp.async.cg.shared.global [%0], [%1], 16;" :: "r"(s), "l"(g));
}
__device__ __forceinline__ void cpa_commit() { asm volatile("cp.async.commit_group;"); }
__device__ __forceinline__ void cpa_wait1()  { asm volatile("cp.async.wait_group 1;"); }
__device__ __forceinline__ void cpa_wait0()  { asm volatile("cp.async.wait_group 0;"); }

#define A_LD 136    // 128 K + 8 pad (halves)
#define B_LD 136    // 128 N + 8 pad

// ---------------------------------------------------------------------------
// gemm2: 512 threads, 16 warps (4m x 4n), warp 32x32, fp16 1-term.
// BK = 128 per stage, 2-stage cp.async pipeline.
//   EPI 0: Cf[bz slice] = acc
//   EPI 1: Cw = fp16(silu(acc))
//   EPI 2: Cf += acc ; Cw = fp16(Cf)
// ---------------------------------------------------------------------------
template<int MTILES, int EPI>
__global__ void __launch_bounds__(512)
gemm2(const __half* __restrict__ Aw, const __half* __restrict__ Bw,
      float* __restrict__ Cf, __half* __restrict__ Cw,
      int lda, int ldb, int ldc, int kchunk, int cslice)
{
    constexpr int BM = MTILES * 64;
    constexpr int A_E = BM * A_LD;
    constexpr int B_E = 128 * B_LD;
    constexpr int STAGE_B = (A_E + B_E) * 2;
    constexpr int OFS_B = A_E * 2;

    extern __shared__ __align__(16) char smem[];
    const uint32_t sb = smem_u32(smem);

    const int tid  = threadIdx.x;
    const int lane = tid & 31;
    const int wid  = tid >> 5;
    const int wm = (wid >> 2) * (MTILES * 16);
    const int wn = (wid & 3) * 32;
    const int mbase = blockIdx.y * BM;
    const int nbase = blockIdx.x * 128;
    const int kbeg  = blockIdx.z * kchunk;
    const int niter = kchunk >> 7;

    float acc[MTILES][4][4];
#pragma unroll
    for (int i = 0; i < MTILES; i++)
#pragma unroll
        for (int j = 0; j < 4; j++)
#pragma unroll
            for (int f = 0; f < 4; f++) acc[i][j][f] = 0.f;

    auto issue = [&](int st, int k0) {
        const uint32_t s0 = sb + st * STAGE_B;
        // A: BM rows x 16 chunks (8 halves each)
#pragma unroll
        for (int i = 0; i < BM * 16 / 512; i++) {
            const int q = tid + i * 512;
            const int row = q >> 4, c16 = q & 15;
            const size_t ga = (size_t)(mbase + row) * lda + k0 + c16 * 8;
            cpa16(s0 + (uint32_t)(row * A_LD + c16 * 8) * 2, Aw + ga);
        }
        // B: 128 k-rows x 16 chunks = 2048
#pragma unroll
        for (int i = 0; i < 4; i++) {
            const int q = tid + i * 512;
            const int kr = q >> 4, c16 = q & 15;
            const size_t gb = (size_t)(k0 + kr) * ldb + nbase + c16 * 8;
            cpa16(s0 + OFS_B + (uint32_t)(kr * B_LD + c16 * 8) * 2, Bw + gb);
        }
    };

    issue(0, kbeg);
    cpa_commit();

    for (int c = 0; c < niter; ++c) {
        if (c + 1 < niter) {
            issue((c + 1) & 1, kbeg + (c + 1) * 128);
            cpa_commit();
            cpa_wait1();
        } else {
            cpa_wait0();
        }
        __syncthreads();

        const uint32_t s0 = sb + (c & 1) * STAGE_B;
#pragma unroll
        for (int ks = 0; ks < 128; ks += 16) {
            uint32_t Bf[4][2];
#pragma unroll
            for (int g = 0; g < 2; g++) {
                const uint32_t off = (uint32_t)((ks + (lane & 15)) * B_LD
                                                + wn + g * 16 + (lane >> 4) * 8) * 2;
                ldmT(Bf[2*g][0], Bf[2*g][1], Bf[2*g+1][0], Bf[2*g+1][1], s0 + OFS_B + off);
            }
#pragma unroll
            for (int mt = 0; mt < MTILES; mt++) {
                uint32_t Af[4];
                const uint32_t offA = (uint32_t)((wm + mt * 16 + (lane & 15)) * A_LD
                                                 + ks + (lane >> 4) * 8) * 2;
                ldmA(Af, s0 + offA);
#pragma unroll
                for (int nt = 0; nt < 4; nt++) mma16816(acc[mt][nt], Af, Bf[nt]);
            }
        }
        __syncthreads();
    }

    float* Cb = (EPI == 0) ? (Cf + (size_t)blockIdx.z * cslice) : Cf;
    const int tr = lane >> 2, tc = (lane & 3) * 2;
#pragma unroll
    for (int mt = 0; mt < MTILES; mt++) {
#pragma unroll
        for (int nt = 0; nt < 4; nt++) {
#pragma unroll
            for (int half = 0; half < 2; half++) {
                const int row = mbase + wm + mt * 16 + tr + half * 8;
                const int col = nbase + wn + nt * 8 + tc;
                float2 v = make_float2(acc[mt][nt][half * 2], acc[mt][nt][half * 2 + 1]);
                if (EPI == 0) {
                    *(float2*)(Cb + (size_t)row * ldc + col) = v;
                } else if (EPI == 1) {
                    v.x = silu_f(v.x); v.y = silu_f(v.y);
                    *(uint32_t*)(Cw + (size_t)row * ldc + col) = cvt2h(v.x, v.y);
                } else {
                    float* p = Cb + (size_t)row * ldc + col;
                    float2 o = *(float2*)p;
                    v.x += o.x; v.y += o.y;
                    *(float2*)p = v;
                    *(uint32_t*)(Cw + (size_t)row * ldc + col) = cvt2h(v.x, v.y);
                }
            }
        }
    }
}

// ---------------------------------------------------------------------------
// fp32 -> fp16 converts
// ---------------------------------------------------------------------------
__global__ void convert_k(const float* __restrict__ src, __half* __restrict__ dst, int n4)
{
    const int i = blockIdx.x * blockDim.x + threadIdx.x;
    if (i >= n4) return;
    const float4 v = ((const float4*)src)[i];
    ((uint2*)dst)[i] = make_uint2(cvt2h(v.x, v.y), cvt2h(v.z, v.w));
}

#define N4_WIN  (NLAY * Dm * 2 * INNER / 4)
#define N4_WOUT (NLAY * INNER * Dm / 4)
#define N4_WM1  (NLAY * Dm * MLPD / 4)
#define N4_WM2  (NLAY * MLPD * Dm / 4)
#define N4_TOT  (N4_WIN + N4_WOUT + N4_WM1 + N4_WM2)

__global__ void convert_weights_k(const float* __restrict__ win, const float* __restrict__ wout,
                                  const float* __restrict__ wm1, const float* __restrict__ wm2,
                                  __half* __restrict__ dwin, __half* __restrict__ dwout,
                                  __half* __restrict__ dwm1, __half* __restrict__ dwm2)
{
    int i = blockIdx.x * blockDim.x + threadIdx.x;
    if (i >= N4_TOT) return;
    const float* s;
    __half* d;
    if (i < N4_WIN)                       { s = win;  d = dwin; }
    else if ((i -= N4_WIN) < N4_WOUT)     { s = wout; d = dwout; }
    else if ((i -= N4_WOUT) < N4_WM1)     { s = wm1;  d = dwm1; }
    else { i -= N4_WM1;                     s = wm2;  d = dwm2; }
    const float4 v = ((const float4*)s)[i];
    ((uint2*)d)[i] = make_uint2(cvt2h(v.x, v.y), cvt2h(v.z, v.w));
}

// ---------------------------------------------------------------------------
// Scan kernels
// ---------------------------------------------------------------------------
__global__ void scan_carry_k(const float* __restrict__ ug, const float* __restrict__ Avec,
                             float* __restrict__ carry)
{
    const int idx = blockIdx.x * blockDim.x + threadIdx.x;
    const int c = idx & (INNER - 1);
    const int gch = idx >> 10;
    const float a = Avec[c];
    const float* up = ug + (size_t)gch * CHLEN * (2 * INNER) + c;
    float hv = 0.f;
#pragma unroll 8
    for (int t = 0; t < CHLEN; t++)
        hv = fmaf(a, hv, up[(size_t)t * (2 * INNER)]);
    carry[idx] = hv;
}

__global__ void combine_k(const float* __restrict__ carry, const float* __restrict__ Avec,
                          float* __restrict__ sin_)
{
    const int idx = blockIdx.x * blockDim.x + threadIdx.x;
    const int c = idx & (INNER - 1);
    const int q = idx >> 10;
    const float a = Avec[c];
    float achunk = a;
#pragma unroll
    for (int i = 0; i < 6; i++) achunk *= achunk;   // a^64
    float s = 0.f;
    for (int k = 0; k < NCH; k++) {
        const size_t o = (size_t)(q * NCH + k) * INNER + c;
        sin_[o] = s;
        s = fmaf(achunk, s, carry[o]);
    }
}

// Final scan + gate. Base pass (stateOut != nullptr, len == CHLEN): also writes
// layer state checkpoints st[q,i] = h_{starts[q,i]-1} (0 if start==0), using
// ascending nextStart tracking. Segment pass: stateOut == nullptr, len == SEGLEN.
__global__ void scan_final_gate_k(const float* __restrict__ ug, const float* __restrict__ Avec,
                                  const float* __restrict__ sin_,
                                  float* __restrict__ stateOut, const int* __restrict__ starts,
                                  __half* __restrict__ pw, int len)
{
    const int idx = blockIdx.x * blockDim.x + threadIdx.x;
    const int c = idx & (INNER - 1);
    const int gch = idx >> 10;
    const float a = Avec[c];
    const float* up = ug + (size_t)gch * len * (2 * INNER) + c;
    const float* gp = up + INNER;
    __half* pp = pw + (size_t)gch * len * INNER + c;
    float hv = sin_[idx];

    int nextS = 0x7fffffff, si = 0, q = 0, t0 = 0;
    if (stateOut) {
        q = gch / NCH;                       // base sequence index (batch)
        t0 = (gch % NCH) * CHLEN;            // global t offset of this chunk
        if (t0 == 0) {
            while (si < NSEG && starts[q * NSEG + si] == 0) {
                stateOut[((size_t)q * NSEG + si) * INNER + c] = 0.f;
                si++;
            }
        } else {
            while (si < NSEG && starts[q * NSEG + si] <= t0) si++;
        }
        if (si < NSEG) nextS = starts[q * NSEG + si];
    }

#pragma unroll 4
    for (int t = 0; t < len; t++) {
        hv = fmaf(a, hv, up[(size_t)t * (2 * INNER)]);
        if (stateOut && (t0 + t + 1) == nextS) {
            stateOut[((size_t)q * NSEG + si) * INNER + c] = hv;
            si++;
            nextS = (si < NSEG) ? starts[q * NSEG + si] : 0x7fffffff;
        }
        const float p = silu_f(gp[(size_t)t * (2 * INNER)]) * hv;
        pp[(size_t)t * INNER] = __float2half_rn(p);
    }
}

// ---------------------------------------------------------------------------
// Small kernels
// ---------------------------------------------------------------------------
__global__ void compute_starts_k(const int* __restrict__ seg, int* __restrict__ starts,
                                 int* __restrict__ ends)
{
    int b = threadIdx.x;
    if (b >= Bsz) return;
    int cnt = 0;
    for (int t = 0; t < Lseq && cnt < NSEG; t++)
        if (seg[b * Lseq + t] != 0) starts[b * NSEG + cnt++] = t;
    while (cnt < NSEG) { starts[b * NSEG + cnt] = 0; cnt++; }
    for (int i = 0; i < NSEG - 1; i++) ends[b * NSEG + i] = starts[b * NSEG + i + 1];
    ends[b * NSEG + NSEG - 1] = Lseq;
}

__global__ void build_inputs_k(const int* __restrict__ ids, const float* __restrict__ E,
                               const float* __restrict__ part,
                               float* __restrict__ x, __half* __restrict__ xw,
                               const int* __restrict__ starts, const int* __restrict__ ends)
{
    const int bid = blockIdx.x;
    if (bid < NROWS) {
        const int id = ids[bid];
        const float4 v = ((const float4*)(E + (size_t)id * Dm))[threadIdx.x];
        ((float4*)(x + (size_t)bid * Dm))[threadIdx.x] = v;
        ((uint2*)(xw + (size_t)bid * Dm))[threadIdx.x] =
            make_uint2(cvt2h(v.x, v.y), cvt2h(v.z, v.w));
    } else {
        const int r = bid - NROWS;
        const int q = r >> 7;
        const int t = r & (SEGLEN - 1);
        const int b = q >> 3;
        const int s = starts[q], e = ends[q];
        const int pos = s + t;
        float4 v = make_float4(0.f, 0.f, 0.f, 0.f);
        if (pos < e && pos < Lseq) {
            const size_t base = ((size_t)b * Lseq + pos) * Dm;
#pragma unroll
            for (int p = 0; p < DEC_SK; p++) {
                const float4 w =
                    ((const float4*)(part + (size_t)p * NROWS * Dm + base))[threadIdx.x];
                v.x += w.x; v.y += w.y; v.z += w.z; v.w += w.w;
            }
        }
        ((float4*)(x + (size_t)bid * Dm))[threadIdx.x] = v;
        ((uint2*)(xw + (size_t)bid * Dm))[threadIdx.x] =
            make_uint2(cvt2h(v.x, v.y), cvt2h(v.z, v.w));
    }
}

__global__ void extract_last_k(const float* __restrict__ xs, float* __restrict__ last,
                               const int* __restrict__ starts, const int* __restrict__ ends)
{
    const int q = blockIdx.x;
    int len = ends[q] - starts[q];
    if (len > SEGLEN) len = SEGLEN;
    if (len < 1) len = 1;
    const float4* s = (const float4*)(xs + ((size_t)q * SEGLEN + (len - 1)) * Dm);
    float4* d = (float4*)(last + (size_t)q * Dm);
    d[threadIdx.x] = s[threadIdx.x];
}

__global__ void head_k(const float* __restrict__ last,
                       const float* __restrict__ muW, const float* __restrict__ mub,
                       const float* __restrict__ lvW, const float* __restrict__ lvb,
                       float* __restrict__ out)
{
    const int o = blockIdx.x * blockDim.x + threadIdx.x;
    const int which = o >> 13;
    const int rem = o & 8191;
    const int r = rem >> 9, d = rem & 511;
    const float* W = which ? lvW : muW;
    const float* bias = which ? lvb : mub;
    const float* lr = last + (size_t)r * Dm;
    float acc = bias[d];
#pragma unroll 8
    for (int k = 0; k < Dm; k++) acc = fmaf(lr[k], W[(size_t)k * Dm + d], acc);
    out[o] = acc;
}

// ---------------------------------------------------------------------------
// Orchestration (my launch #3 = dec GEMM for ncu window)
// ---------------------------------------------------------------------------
extern "C" void kernel_launch(void* const* d_in, const int* in_sizes, int n_in,
                              void* d_out, int out_size)
{
    const float* decoder_output = (const float*)d_in[0];
    const int*   input_ids      = (const int*)  d_in[1];
    const int*   seg_idx        = (const int*)  d_in[2];
    const float* E              = (const float*)d_in[3];
    const float* Aparam         = (const float*)d_in[4];
    const float* Win            = (const float*)d_in[5];
    const float* Wout           = (const float*)d_in[6];
    const float* Wm1            = (const float*)d_in[7];
    const float* Wm2            = (const float*)d_in[8];
    const float* muW            = (const float*)d_in[9];
    const float* mub            = (const float*)d_in[10];
    const float* lvW            = (const float*)d_in[11];
    const float* lvb            = (const float*)d_in[12];
    float* out = (float*)d_out;

    float *x, *decpart, *ug, *state, *carry, *sins, *last;
    int *starts, *ends;
    __half *decAw, *xw, *pw, *mlpw, *ew, *winw, *woutw, *wm1w, *wm2w;
    cudaGetSymbolAddress((void**)&x,       g_x);
    cudaGetSymbolAddress((void**)&decpart, g_decpart);
    cudaGetSymbolAddress((void**)&ug,      g_ug);
    cudaGetSymbolAddress((void**)&state,   g_state);
    cudaGetSymbolAddress((void**)&carry,   g_carry);
    cudaGetSymbolAddress((void**)&sins,    g_sin);
    cudaGetSymbolAddress((void**)&last,    g_last);
    cudaGetSymbolAddress((void**)&starts,  g_starts);
    cudaGetSymbolAddress((void**)&ends,    g_ends);
    cudaGetSymbolAddress((void**)&decAw,   g_decAw);
    cudaGetSymbolAddress((void**)&xw,      g_xw);
    cudaGetSymbolAddress((void**)&pw,      g_pw);
    cudaGetSymbolAddress((void**)&mlpw,    g_mlpw);
    cudaGetSymbolAddress((void**)&ew,      g_Ew);
    cudaGetSymbolAddress((void**)&winw,    g_Winw);
    cudaGetSymbolAddress((void**)&woutw,   g_Woutw);
    cudaGetSymbolAddress((void**)&wm1w,    g_Wm1w);
    cudaGetSymbolAddress((void**)&wm2w,    g_Wm2w);

    constexpr int SMEM2 = (128 * A_LD + 128 * B_LD) * 2 * 2;  // 139,264 B
    constexpr int SMEM1 = (64  * A_LD + 128 * B_LD) * 2 * 2;  // 104,448 B
    cudaFuncSetAttribute(gemm2<2, 0>, cudaFuncAttributeMaxDynamicSharedMemorySize, SMEM2);
    cudaFuncSetAttribute(gemm2<2, 1>, cudaFuncAttributeMaxDynamicSharedMemorySize, SMEM2);
    cudaFuncSetAttribute(gemm2<1, 2>, cudaFuncAttributeMaxDynamicSharedMemorySize, SMEM1);

    // #0..#2
    compute_starts_k<<<1, 32>>>(seg_idx, starts, ends);
    convert_k<<<(VOC * Dm / 4 + 255) / 256, 256>>>(E, ew, VOC * Dm / 4);
    convert_k<<<(NROWS * VOC / 4 + 255) / 256, 256>>>(decoder_output, decAw, NROWS * VOC / 4);

    // #3: dec GEMM (split-K=5, 1-term fp16, BK=128) — ncu capture target
    gemm2<2, 0><<<dim3(Dm / 128, NROWS / 128, DEC_SK), 512, SMEM2>>>(
        decAw, ew, decpart, nullptr, VOC, Dm, Dm, DEC_KSLICE, NROWS * Dm);

    build_inputs_k<<<XROWS, 128>>>(input_ids, E, decpart, x, xw, starts, ends);
    convert_weights_k<<<(N4_TOT + 255) / 256, 256>>>(Win, Wout, Wm1, Wm2,
                                                     winw, woutw, wm1w, wm2w);

    // -------- Merged layer loop (base rows 0..2047, segment rows 2048..4095) --------
    for (int l = 0; l < NLAY; l++) {
        const size_t oWin  = (size_t)l * Dm * 2 * INNER;
        const size_t oWout = (size_t)l * INNER * Dm;
        const size_t oWm1  = (size_t)l * Dm * MLPD;
        const size_t oWm2  = (size_t)l * MLPD * Dm;
        const float* Al    = Aparam + (size_t)l * INNER;
        float* stl = state + (size_t)l * Bsz * NSEG * INNER;

        gemm2<2, 0><<<dim3((2 * INNER) / 128, XROWS / 128, 1), 512, SMEM2>>>(
            xw, winw + oWin, ug, nullptr, Dm, 2 * INNER, 2 * INNER, Dm, 0);
        // base scan: carries -> combine -> final (+fused state checkpointing)
        scan_carry_k<<<(Bsz * NCH * INNER) / 256, 256>>>(ug, Al, carry);
        combine_k<<<(Bsz * INNER) / 256, 256>>>(carry, Al, sins);
        scan_final_gate_k<<<(Bsz * NCH * INNER) / 256, 256>>>(
            ug, Al, sins, stl, starts, pw, CHLEN);
        // segment scan from checkpointed states
        scan_final_gate_k<<<(Bsz * NSEG * INNER) / 256, 256>>>(
            ug + (size_t)NROWS * 2 * INNER, Al, stl, nullptr, nullptr,
            pw + (size_t)NROWS * INNER, SEGLEN);
        gemm2<1, 2><<<dim3(Dm / 128, XROWS / 64, 1), 512, SMEM1>>>(
            pw, woutw + oWout, x, xw, INNER, Dm, Dm, INNER, 0);
        gemm2<2, 1><<<dim3(MLPD / 128, XROWS / 128, 1), 512, SMEM2>>>(
            xw, wm1w + oWm1, nullptr, mlpw, Dm, MLPD, MLPD, Dm, 0);
        gemm2<1, 2><<<dim3(Dm / 128, XROWS / 64, 1), 512, SMEM1>>>(
            mlpw, wm2w + oWm2, x, xw, MLPD, Dm, Dm, MLPD, 0);
    }

    extract_last_k<<<Bsz * NSEG, 128>>>(x + (size_t)NROWS * Dm, last, starts, ends);
    head_k<<<(2 * Bsz * NSEG * Dm) / 256, 256>>>(last, muW, mub, lvW, lvb, out);
}